// round 6
// baseline (speedup 1.0000x reference)
#include <cuda_runtime.h>
#include <cuda_bf16.h>
#include <math.h>

// Problem constants
#define B_   2048
#define TIN  365
#define CIN0 4
#define KPROT 32
#define LOUT_ 366
#define LSTR_ 368   // padded time stride (16B aligned rows)

// ---------------- scratch (device globals; no allocs allowed) ----------------
__device__ float  g_y1[2048ull*128*LSTR_];   // conv1 pre-BN output
__device__ float  g_y2[2048ull*256*LSTR_];   // conv2 pre-BN output
__device__ float  g_y3[2048ull*128*LSTR_];   // conv3 pre-BN output
__device__ float  g_w1r[128*4*8];
__device__ float  g_w2r[256*128*5];
__device__ float  g_w3r[128*256*3];
__device__ double g_sum[512];                // [0,128) L1, [128,384) L2, [384,512) L3
__device__ double g_sq [512];
__device__ float  g_bnS[512];
__device__ float  g_bnT[512];
__device__ float  g_off[2048*128];           // tanh offsets (B, K*C)

// ---------------- small kernels ----------------
__global__ void zero_stats(double* s, double* q) {
    int i = blockIdx.x * 256 + threadIdx.x;
    if (i < 512) { s[i] = 0.0; q[i] = 0.0; }
}

// (CO,CI,KW) -> [(ci*KW+k)*CO + co]
__global__ void reorder_w(const float* __restrict__ w, float* __restrict__ wr,
                          int CO, int CI, int KW) {
    int idx = blockIdx.x * 256 + threadIdx.x;
    int n = CO * CI * KW;
    if (idx < n) {
        int k  = idx % KW;
        int r  = idx / KW;
        int ci = r % CI;
        int co = r / CI;
        wr[((size_t)ci * KW + k) * CO + co] = w[idx];
    }
}

__global__ void finalize_bn(const double* __restrict__ sum, const double* __restrict__ sq,
                            const float* __restrict__ g, const float* __restrict__ be,
                            float* __restrict__ S, float* __restrict__ T,
                            int C, double invN) {
    int c = threadIdx.x + blockIdx.x * blockDim.x;
    if (c < C) {
        double mu  = sum[c] * invN;
        double var = sq[c] * invN - mu * mu;
        double s   = (double)g[c] * rsqrt(var + 1e-5);
        S[c] = (float)s;
        T[c] = be[c] - (float)(mu * s);
    }
}

// ---------------- conv + (input BN/ReLU) + bias + stats ----------------
// out[b,co,t] = bias[co] + sum_{ci,k} w[co,ci,k] * a(b,ci,t+k-PAD)
// a = input_seq (FIRST) or relu(bnS*y + bnT)
template<bool FIRST, int CIN, int COUT, int KW, int PAD, int CK>
__global__ __launch_bounds__(256, 2)
void conv_bn(const float* __restrict__ in, const float* __restrict__ wre,
             const float* __restrict__ bias,
             const float* __restrict__ bnS, const float* __restrict__ bnT,
             float* __restrict__ out,
             double* __restrict__ gsum, double* __restrict__ gsq,
             int LIN, int INSTR, int LOUT, int OUTSTR) {
    constexpr int COT = 128;
    constexpr int TT  = 128;
    constexpr int W   = TT + KW - 1;
    constexpr int WS  = ((W + 4 + 3) / 4) * 4;    // padded row stride
    constexpr int NA  = ((8 + KW - 1 + 3) / 4) * 4;

    __shared__ float As[CK][WS];
    __shared__ float Ws[CK][KW][COT];
    __shared__ float sSum[COT];
    __shared__ float sSq[COT];

    const int t0  = blockIdx.x * TT;
    const int co0 = blockIdx.y * COT;
    const int b   = blockIdx.z;
    const int tid = threadIdx.x;
    const int tc  = tid & 15;   // co group
    const int tr  = tid >> 4;   // t group

    for (int i = tid; i < COT; i += 256) { sSum[i] = 0.f; sSq[i] = 0.f; }

    float acc[8][8];
#pragma unroll
    for (int j = 0; j < 8; j++)
#pragma unroll
        for (int i = 0; i < 8; i++) acc[j][i] = 0.f;

    for (int ci0 = 0; ci0 < CIN; ci0 += CK) {
        __syncthreads();
        // load A tile (BN+ReLU applied here for non-first layers)
        for (int idx = tid; idx < CK * W; idx += 256) {
            int ci = idx / W, col = idx % W;
            int tg = t0 - PAD + col;
            float v = 0.f;
            if (tg >= 0 && tg < LIN) {
                if (FIRST) {
                    v = in[((size_t)b * LIN + tg) * CIN + (ci0 + ci)];
                } else {
                    v = in[((size_t)b * CIN + ci0 + ci) * INSTR + tg];
                    v = fmaxf(fmaf(bnS[ci0 + ci], v, bnT[ci0 + ci]), 0.f);
                }
            }
            As[ci][col] = v;
        }
        // load W tile (pre-reordered: [(ci*KW+k)*COUT + co])
        for (int idx = tid; idx < CK * KW * COT; idx += 256) {
            int co = idx & (COT - 1);
            int r  = idx >> 7;
            int k  = r % KW;
            int ci = r / KW;
            Ws[ci][k][co] = wre[((size_t)(ci0 + ci) * KW + k) * COUT + co0 + co];
        }
        __syncthreads();
#pragma unroll 1
        for (int ci = 0; ci < CK; ci++) {
            float a[NA];
#pragma unroll
            for (int q = 0; q < NA / 4; q++)
                *(float4*)&a[4 * q] = *(const float4*)&As[ci][tr * 8 + 4 * q];
#pragma unroll
            for (int k = 0; k < KW; k++) {
                float wv[8];
                *(float4*)&wv[0] = *(const float4*)&Ws[ci][k][tc * 8];
                *(float4*)&wv[4] = *(const float4*)&Ws[ci][k][tc * 8 + 4];
#pragma unroll
                for (int j = 0; j < 8; j++)
#pragma unroll
                    for (int i = 0; i < 8; i++)
                        acc[j][i] = fmaf(wv[j], a[k + i], acc[j][i]);
            }
        }
    }

    // bias + per-channel stats (only valid t)
    const bool fullT = (t0 + TT <= LOUT);
    float bj[8];
#pragma unroll
    for (int j = 0; j < 8; j++) bj[j] = bias[co0 + tc * 8 + j];
#pragma unroll
    for (int j = 0; j < 8; j++) {
        float s = 0.f, s2 = 0.f;
#pragma unroll
        for (int i = 0; i < 8; i++) {
            float v = acc[j][i] + bj[j];
            acc[j][i] = v;
            if (fullT || (t0 + tr * 8 + i < LOUT)) { s += v; s2 += v * v; }
        }
        atomicAdd(&sSum[tc * 8 + j], s);
        atomicAdd(&sSq[tc * 8 + j], s2);
    }
    // store
#pragma unroll
    for (int j = 0; j < 8; j++) {
        size_t base = ((size_t)b * COUT + co0 + tc * 8 + j) * OUTSTR + t0 + tr * 8;
        if (fullT) {
            *(float4*)&out[base]     = make_float4(acc[j][0], acc[j][1], acc[j][2], acc[j][3]);
            *(float4*)&out[base + 4] = make_float4(acc[j][4], acc[j][5], acc[j][6], acc[j][7]);
        } else {
#pragma unroll
            for (int i = 0; i < 8; i++)
                if (t0 + tr * 8 + i < LOUT) out[base + i] = acc[j][i];
        }
    }
    __syncthreads();
    for (int c = tid; c < COT; c += 256) {
        atomicAdd(&gsum[co0 + c], (double)sSum[c]);
        atomicAdd(&gsq[co0 + c],  (double)sSq[c]);
    }
}

// ---------------- pool + fc + offset head ----------------
__global__ void pool_fc_off(const float* __restrict__ y3,
                            const float* __restrict__ s3, const float* __restrict__ t3,
                            const float* __restrict__ fcw, const float* __restrict__ fcb,
                            const float* __restrict__ offw, const float* __restrict__ offb,
                            float* __restrict__ goff) {
    int b = blockIdx.x;
    int c = threadIdx.x;   // 128 threads
    __shared__ float pooled[128];
    __shared__ float feat[128];

    const float* row = y3 + ((size_t)b * 128 + c) * LSTR_;
    float s = s3[c], t = t3[c], acc = 0.f;
    int i = 0;
    for (; i + 4 <= LOUT_; i += 4) {
        float4 v = *(const float4*)&row[i];
        acc += fmaxf(fmaf(s, v.x, t), 0.f) + fmaxf(fmaf(s, v.y, t), 0.f)
             + fmaxf(fmaf(s, v.z, t), 0.f) + fmaxf(fmaf(s, v.w, t), 0.f);
    }
    for (; i < LOUT_; i++) acc += fmaxf(fmaf(s, row[i], t), 0.f);
    pooled[c] = acc * (1.f / (float)LOUT_);
    __syncthreads();

    float f = fcb[c];
#pragma unroll 4
    for (int q = 0; q < 32; q++) {
        float4 w = *(const float4*)&fcw[c * 128 + 4 * q];
        float4 p = *(const float4*)&pooled[4 * q];
        f = fmaf(w.x, p.x, f); f = fmaf(w.y, p.y, f);
        f = fmaf(w.z, p.z, f); f = fmaf(w.w, p.w, f);
    }
    feat[c] = f;
    __syncthreads();

    float o = offb[c];
#pragma unroll 4
    for (int q = 0; q < 32; q++) {
        float4 w = *(const float4*)&offw[c * 128 + 4 * q];
        float4 p = *(const float4*)&feat[4 * q];
        o = fmaf(w.x, p.x, o); o = fmaf(w.y, p.y, o);
        o = fmaf(w.z, p.z, o); o = fmaf(w.w, p.w, o);
    }
    goff[(size_t)b * 128 + c] = tanhf(o);
}

// ---------------- distances + argmin + gather output ----------------
__global__ void dist_out(const float* __restrict__ x, const float* __restrict__ mask,
                         const float* __restrict__ protos, const float* __restrict__ goff,
                         float* __restrict__ out) {
    int b = blockIdx.x, tid = threadIdx.x;   // 256 threads
    __shared__ float4 xs[TIN];
    __shared__ float  ms[TIN];
    __shared__ float  sdist[KPROT];
    __shared__ int    sbest;

    for (int t = tid; t < TIN; t += 256) {
        xs[t] = *(const float4*)&x[((size_t)b * TIN + t) * 4];
        ms[t] = mask[(size_t)b * TIN + t];
    }
    if (tid < KPROT) sdist[tid] = 0.f;
    __syncthreads();

    for (int k = 0; k < KPROT; k++) {
        float4 ov = *(const float4*)&goff[(size_t)b * 128 + k * 4];
        float local = 0.f;
        for (int t = tid; t < TIN; t += 256) {
            float4 p  = *(const float4*)&protos[((size_t)k * TIN + t) * 4];
            float4 xv = xs[t];
            float d0 = xv.x - p.x - ov.x;
            float d1 = xv.y - p.y - ov.y;
            float d2 = xv.z - p.z - ov.z;
            float d3 = xv.w - p.w - ov.w;
            local += ms[t] * (d0 * d0 + d1 * d1 + d2 * d2 + d3 * d3);
        }
#pragma unroll
        for (int o = 16; o; o >>= 1) local += __shfl_xor_sync(0xffffffffu, local, o);
        if ((tid & 31) == 0) atomicAdd(&sdist[k], local);
    }
    __syncthreads();
    if (tid < 32) {
        float v = sdist[tid];
        int  idx = tid;
#pragma unroll
        for (int o = 16; o; o >>= 1) {
            float v2 = __shfl_xor_sync(0xffffffffu, v, o);
            int  i2  = __shfl_xor_sync(0xffffffffu, idx, o);
            if (v2 < v || (v2 == v && i2 < idx)) { v = v2; idx = i2; }
        }
        if (tid == 0) sbest = idx;
    }
    __syncthreads();
    int best = sbest;
    float4 ob = *(const float4*)&goff[(size_t)b * 128 + best * 4];
    for (int t = tid; t < TIN; t += 256) {
        float4 p = *(const float4*)&protos[((size_t)best * TIN + t) * 4];
        *(float4*)&out[((size_t)b * TIN + t) * 4] =
            make_float4(p.x + ob.x, p.y + ob.y, p.z + ob.z, p.w + ob.w);
    }
}

// ---------------- launcher ----------------
extern "C" void kernel_launch(void* const* d_in, const int* in_sizes, int n_in,
                              void* d_out, int out_size) {
    (void)in_sizes; (void)n_in; (void)out_size;
    const float* x      = (const float*)d_in[0];
    const float* mask   = (const float*)d_in[2];
    const float* protos = (const float*)d_in[3];
    const float* w1  = (const float*)d_in[4];
    const float* b1  = (const float*)d_in[5];
    const float* g1  = (const float*)d_in[6];
    const float* be1 = (const float*)d_in[7];
    const float* w2  = (const float*)d_in[8];
    const float* b2  = (const float*)d_in[9];
    const float* g2  = (const float*)d_in[10];
    const float* be2 = (const float*)d_in[11];
    const float* w3  = (const float*)d_in[12];
    const float* b3  = (const float*)d_in[13];
    const float* g3  = (const float*)d_in[14];
    const float* be3 = (const float*)d_in[15];
    const float* fcw = (const float*)d_in[16];
    const float* fcb = (const float*)d_in[17];
    const float* offw = (const float*)d_in[18];
    const float* offb = (const float*)d_in[19];
    float* out = (float*)d_out;

    float *y1, *y2, *y3, *w1r, *w2r, *w3r, *bnS, *bnT, *goff;
    double *gsum, *gsq;
    cudaGetSymbolAddress((void**)&y1,  g_y1);
    cudaGetSymbolAddress((void**)&y2,  g_y2);
    cudaGetSymbolAddress((void**)&y3,  g_y3);
    cudaGetSymbolAddress((void**)&w1r, g_w1r);
    cudaGetSymbolAddress((void**)&w2r, g_w2r);
    cudaGetSymbolAddress((void**)&w3r, g_w3r);
    cudaGetSymbolAddress((void**)&gsum, g_sum);
    cudaGetSymbolAddress((void**)&gsq,  g_sq);
    cudaGetSymbolAddress((void**)&bnS, g_bnS);
    cudaGetSymbolAddress((void**)&bnT, g_bnT);
    cudaGetSymbolAddress((void**)&goff, g_off);

    const double invN = 1.0 / ((double)B_ * (double)LOUT_);

    zero_stats<<<2, 256>>>(gsum, gsq);
    reorder_w<<<(128 * 4 * 8 + 255) / 256, 256>>>(w1, w1r, 128, 4, 8);
    reorder_w<<<(256 * 128 * 5 + 255) / 256, 256>>>(w2, w2r, 256, 128, 5);
    reorder_w<<<(128 * 256 * 3 + 255) / 256, 256>>>(w3, w3r, 128, 256, 3);

    dim3 gc1(3, 1, B_);
    conv_bn<true, 4, 128, 8, 4, 4><<<gc1, 256>>>(
        x, w1r, b1, nullptr, nullptr, y1, gsum, gsq, TIN, 0, LOUT_, LSTR_);
    finalize_bn<<<1, 256>>>(gsum, gsq, g1, be1, bnS, bnT, 128, invN);

    dim3 gc2(3, 2, B_);
    conv_bn<false, 128, 256, 5, 2, 8><<<gc2, 256>>>(
        y1, w2r, b2, bnS, bnT, y2, gsum + 128, gsq + 128, LOUT_, LSTR_, LOUT_, LSTR_);
    finalize_bn<<<1, 256>>>(gsum + 128, gsq + 128, g2, be2, bnS + 128, bnT + 128, 256, invN);

    dim3 gc3(3, 1, B_);
    conv_bn<false, 256, 128, 3, 1, 16><<<gc3, 256>>>(
        y2, w3r, b3, bnS + 128, bnT + 128, y3, gsum + 384, gsq + 384, LOUT_, LSTR_, LOUT_, LSTR_);
    finalize_bn<<<1, 256>>>(gsum + 384, gsq + 384, g3, be3, bnS + 384, bnT + 384, 128, invN);

    pool_fc_off<<<B_, 128>>>(y3, bnS + 384, bnT + 384, fcw, fcb, offw, offb, goff);
    dist_out<<<B_, 256>>>(x, mask, protos, goff, out);
}

// round 11
// speedup vs baseline: 3.1640x; 3.1640x over previous
#include <cuda_runtime.h>
#include <cuda_bf16.h>
#include <math.h>
#include <cstdint>

// Problem constants
#define B_    2048
#define TIN   365
#define CIN0  4
#define KPROT 32
#define LOUT_ 366
#define LSTR_ 368   // padded time stride

// Does this compilation pass have tcgen05 (arch-specific sm_10xa/f)?
#if !defined(__CUDA_ARCH__)
#define HAS_TC 1   // host pass: body not codegen'd, either branch fine
#elif defined(__CUDA_ARCH_FEAT_SM103_ALL) || defined(__CUDA_ARCH_FEAT_SM100_ALL) || \
      (defined(__CUDA_ARCH_SPECIFIC__) && (__CUDA_ARCH_SPECIFIC__ >= 1000)) || \
      (defined(__CUDA_ARCH_FAMILY_SPECIFIC__) && (__CUDA_ARCH_FAMILY_SPECIFIC__ >= 1000))
#define HAS_TC 1
#else
#define HAS_TC 0
#endif

// ---------------- scratch (device globals; no allocs allowed) ----------------
__device__ float  g_y1[2048ull*128*LSTR_];
__device__ float  g_y2[2048ull*256*LSTR_];
__device__ float  g_y3[2048ull*128*LSTR_];
__device__ float  g_w1r[128*4*8];
__device__ float  g_w2p[327680];   // packed hi/lo tf32 weights layer2
__device__ float  g_w3p[196608];   // packed hi/lo tf32 weights layer3
__device__ double g_sum[512];
__device__ double g_sq [512];
__device__ float  g_bnS[512];
__device__ float  g_bnT[512];
__device__ float  g_off[2048*128];

// ---------------- PTX helpers ----------------
__device__ __forceinline__ uint32_t smem_u32(const void* p) {
    uint32_t a;
    asm("{ .reg .u64 t; cvta.to.shared.u64 t, %1; cvt.u32.u64 %0, t; }" : "=r"(a) : "l"(p));
    return a;
}
__device__ __forceinline__ float rna_tf32(float x) {
    float r; asm("cvt.rna.tf32.f32 %0, %1;" : "=f"(r) : "f"(x)); return r;
}

#define MBARRIER_INIT(mbar, count) \
    asm volatile("mbarrier.init.shared.b64 [%0], %1;" :: "r"((uint32_t)(mbar)), "r"((uint32_t)(count)) : "memory")

#define MBARRIER_WAIT_PARITY(mbar_smem_addr, phase_parity) do { \
    uint32_t _mbar = (uint32_t)(mbar_smem_addr); \
    uint32_t _parity = (uint32_t)(phase_parity); \
    uint32_t _done; \
    asm volatile( \
        "{\n\t" \
        ".reg .pred p;\n\t" \
        "mbarrier.try_wait.parity.acquire.cta.shared::cta.b64 p, [%1], %2;\n\t" \
        "selp.b32 %0, 1, 0, p;\n\t" \
        "}" \
        : "=r"(_done) : "r"(_mbar), "r"(_parity) : "memory"); \
    if (!_done) { \
        asm volatile( \
            "{\n\t" \
            ".reg .pred P1;\n\t" \
            "WAIT_LOOP_%=:\n\t" \
            "mbarrier.try_wait.parity.acquire.cta.shared::cta.b64 P1, [%0], %1, 0x989680;\n\t" \
            "@P1 bra.uni WAIT_DONE_%=;\n\t" \
            "bra.uni WAIT_LOOP_%=;\n\t" \
            "WAIT_DONE_%=:\n\t" \
            "}" \
            :: "r"(_mbar), "r"(_parity) : "memory"); \
    } \
} while(0)

#define FENCE_PROXY_ASYNC() \
    asm volatile("fence.proxy.async.shared::cta;" ::: "memory")

#if HAS_TC
// SMEM descriptor: no swizzle (layout 0), version=1 (Blackwell)
__device__ __forceinline__ uint64_t mk_desc(uint32_t addr, uint32_t lbo, uint32_t sbo) {
    return ((uint64_t)(addr >> 4) & 0x3FFF)
         | (((uint64_t)lbo & 0x3FFF) << 16)
         | (((uint64_t)sbo & 0x3FFF) << 32)
         | (1ull << 46);
}

#define TCGEN05_ALLOC(smem_result_addr, nCols) \
    asm volatile("tcgen05.alloc.cta_group::1.sync.aligned.shared::cta.b32 [%0], %1;" \
        :: "r"((uint32_t)(smem_result_addr)), "r"((uint32_t)(nCols)) : "memory")
#define TCGEN05_DEALLOC(tmem_addr, nCols) \
    asm volatile("tcgen05.dealloc.cta_group::1.sync.aligned.b32 %0, %1;" :: "r"(tmem_addr), "r"(nCols))
#define TCGEN05_RELINQUISH() \
    asm volatile("tcgen05.relinquish_alloc_permit.cta_group::1.sync.aligned;")
#define TCGEN05_COMMIT(mbar) \
    asm volatile("tcgen05.commit.cta_group::1.mbarrier::arrive::one.shared::cluster.b64 [%0];" \
        :: "r"((uint32_t)(mbar)) : "memory")
#define TCGEN05_FENCE_AFTER() \
    asm volatile("tcgen05.fence::after_thread_sync;" ::: "memory")
#define TCGEN05_FENCE_BEFORE() \
    asm volatile("tcgen05.fence::before_thread_sync;" ::: "memory")
#define TCGEN05_WAIT_LD() \
    asm volatile("tcgen05.wait::ld.sync.aligned;" ::: "memory")

__device__ __forceinline__ void mma_tf32_ss(uint32_t d_tmem, uint64_t a_desc, uint64_t b_desc,
                                            uint32_t idesc, uint32_t enable) {
    asm volatile(
        "{\n\t"
        ".reg .pred p;\n\t"
        "setp.ne.u32 p, %4, 0;\n\t"
        "tcgen05.mma.cta_group::1.kind::tf32 [%0], %1, %2, %3, {%5, %5, %5, %5}, p;\n\t"
        "}"
        :: "r"(d_tmem), "l"(a_desc), "l"(b_desc), "r"(idesc), "r"(enable), "r"(0u)
        : "memory");
}

#define TCGEN05_LD_32X32B_X32(r, tmem_addr) \
    asm volatile( \
        "tcgen05.ld.sync.aligned.32x32b.x32.b32 " \
        "{%0, %1, %2, %3, %4, %5, %6, %7, " \
        " %8, %9, %10, %11, %12, %13, %14, %15, " \
        " %16, %17, %18, %19, %20, %21, %22, %23, " \
        " %24, %25, %26, %27, %28, %29, %30, %31}, [%32];" \
        : "=r"((r)[0]),  "=r"((r)[1]),  "=r"((r)[2]),  "=r"((r)[3]), \
          "=r"((r)[4]),  "=r"((r)[5]),  "=r"((r)[6]),  "=r"((r)[7]), \
          "=r"((r)[8]),  "=r"((r)[9]),  "=r"((r)[10]), "=r"((r)[11]), \
          "=r"((r)[12]), "=r"((r)[13]), "=r"((r)[14]), "=r"((r)[15]), \
          "=r"((r)[16]), "=r"((r)[17]), "=r"((r)[18]), "=r"((r)[19]), \
          "=r"((r)[20]), "=r"((r)[21]), "=r"((r)[22]), "=r"((r)[23]), \
          "=r"((r)[24]), "=r"((r)[25]), "=r"((r)[26]), "=r"((r)[27]), \
          "=r"((r)[28]), "=r"((r)[29]), "=r"((r)[30]), "=r"((r)[31]) \
        : "r"(tmem_addr))

// idesc: f32 accum(bit4=1), tf32 a/b (=2 @bits7,10), N=128 (N>>3 @bit17), M=128 (M>>4 @bit24)
#define IDESC_TF32 ((1u<<4) | (2u<<7) | (2u<<10) | (16u<<17) | (8u<<24))
#endif // HAS_TC

// ---------------- small kernels ----------------
__global__ void zero_stats(double* s, double* q) {
    int i = blockIdx.x * 256 + threadIdx.x;
    if (i < 512) { s[i] = 0.0; q[i] = 0.0; }
}

__global__ void reorder_w(const float* __restrict__ w, float* __restrict__ wr,
                          int CO, int CI, int KW) {
    int idx = blockIdx.x * 256 + threadIdx.x;
    int n = CO * CI * KW;
    if (idx < n) {
        int k  = idx % KW;
        int r  = idx / KW;
        int ci = r % CI;
        int co = r / CI;
        wr[((size_t)ci * KW + k) * CO + co] = w[idx];
    }
}

// pack weights to [ct][chunk][s(2)][k(KW)][j(4)][co(128)][e(4)], tf32 hi/lo split
__global__ void pack_w(const float* __restrict__ w, float* __restrict__ wp,
                       int CI, int KW, int CH, int total) {
    int idx = blockIdx.x * 256 + threadIdx.x;
    if (idx >= total) return;
    int e  = idx & 3;
    int co = (idx >> 2) & 127;
    int j  = (idx >> 9) & 3;
    int r  = idx >> 11;
    int k  = r % KW; r /= KW;
    int s  = r & 1;  r >>= 1;
    int chunk = r % CH;
    int ct = r / CH;
    int ci  = chunk * 16 + j * 4 + e;
    int cog = ct * 128 + co;
    float v = w[((size_t)cog * CI + ci) * KW + k];
    float h = rna_tf32(v);
    wp[idx] = s ? rna_tf32(v - h) : h;
}

__global__ void finalize_bn(const double* __restrict__ sum, const double* __restrict__ sq,
                            const float* __restrict__ g, const float* __restrict__ be,
                            float* __restrict__ S, float* __restrict__ T,
                            int C, double invN) {
    int c = threadIdx.x + blockIdx.x * blockDim.x;
    if (c < C) {
        double mu  = sum[c] * invN;
        double var = sq[c] * invN - mu * mu;
        double s   = (double)g[c] * rsqrt(var + 1e-5);
        S[c] = (float)s;
        T[c] = be[c] - (float)(mu * s);
    }
}

// ---------------- conv1 (small; fp32 register-tiled path) ----------------
template<bool FIRST, int CIN, int COUT, int KW, int PAD, int CK>
__global__ __launch_bounds__(256, 2)
void conv_bn(const float* __restrict__ in, const float* __restrict__ wre,
             const float* __restrict__ bias,
             const float* __restrict__ bnS, const float* __restrict__ bnT,
             float* __restrict__ out,
             double* __restrict__ gsum, double* __restrict__ gsq,
             int LIN, int INSTR, int LOUT, int OUTSTR) {
    constexpr int COT = 128;
    constexpr int TT  = 128;
    constexpr int W   = TT + KW - 1;
    constexpr int WS  = ((W + 4 + 3) / 4) * 4;
    constexpr int NA  = ((8 + KW - 1 + 3) / 4) * 4;

    __shared__ float As[CK][WS];
    __shared__ float Ws[CK][KW][COT];
    __shared__ float sSum[COT];
    __shared__ float sSq[COT];

    const int t0  = blockIdx.x * TT;
    const int co0 = blockIdx.y * COT;
    const int b   = blockIdx.z;
    const int tid = threadIdx.x;
    const int tc  = tid & 15;
    const int tr  = tid >> 4;

    for (int i = tid; i < COT; i += 256) { sSum[i] = 0.f; sSq[i] = 0.f; }

    float acc[8][8];
#pragma unroll
    for (int j = 0; j < 8; j++)
#pragma unroll
        for (int i = 0; i < 8; i++) acc[j][i] = 0.f;

    for (int ci0 = 0; ci0 < CIN; ci0 += CK) {
        __syncthreads();
        for (int idx = tid; idx < CK * W; idx += 256) {
            int ci = idx / W, col = idx % W;
            int tg = t0 - PAD + col;
            float v = 0.f;
            if (tg >= 0 && tg < LIN) {
                if (FIRST) {
                    v = in[((size_t)b * LIN + tg) * CIN + (ci0 + ci)];
                } else {
                    v = in[((size_t)b * CIN + ci0 + ci) * INSTR + tg];
                    v = fmaxf(fmaf(bnS[ci0 + ci], v, bnT[ci0 + ci]), 0.f);
                }
            }
            As[ci][col] = v;
        }
        for (int idx = tid; idx < CK * KW * COT; idx += 256) {
            int co = idx & (COT - 1);
            int r  = idx >> 7;
            int k  = r % KW;
            int ci = r / KW;
            Ws[ci][k][co] = wre[((size_t)(ci0 + ci) * KW + k) * COUT + co0 + co];
        }
        __syncthreads();
#pragma unroll 1
        for (int ci = 0; ci < CK; ci++) {
            float a[NA];
#pragma unroll
            for (int q = 0; q < NA / 4; q++)
                *(float4*)&a[4 * q] = *(const float4*)&As[ci][tr * 8 + 4 * q];
#pragma unroll
            for (int k = 0; k < KW; k++) {
                float wv[8];
                *(float4*)&wv[0] = *(const float4*)&Ws[ci][k][tc * 8];
                *(float4*)&wv[4] = *(const float4*)&Ws[ci][k][tc * 8 + 4];
#pragma unroll
                for (int j = 0; j < 8; j++)
#pragma unroll
                    for (int i = 0; i < 8; i++)
                        acc[j][i] = fmaf(wv[j], a[k + i], acc[j][i]);
            }
        }
    }

    const bool fullT = (t0 + TT <= LOUT);
    float bj[8];
#pragma unroll
    for (int j = 0; j < 8; j++) bj[j] = bias[co0 + tc * 8 + j];
#pragma unroll
    for (int j = 0; j < 8; j++) {
        float s = 0.f, s2 = 0.f;
#pragma unroll
        for (int i = 0; i < 8; i++) {
            float v = acc[j][i] + bj[j];
            acc[j][i] = v;
            if (fullT || (t0 + tr * 8 + i < LOUT)) { s += v; s2 += v * v; }
        }
        atomicAdd(&sSum[tc * 8 + j], s);
        atomicAdd(&sSq[tc * 8 + j], s2);
    }
#pragma unroll
    for (int j = 0; j < 8; j++) {
        size_t base = ((size_t)b * COUT + co0 + tc * 8 + j) * OUTSTR + t0 + tr * 8;
        if (fullT) {
            *(float4*)&out[base]     = make_float4(acc[j][0], acc[j][1], acc[j][2], acc[j][3]);
            *(float4*)&out[base + 4] = make_float4(acc[j][4], acc[j][5], acc[j][6], acc[j][7]);
        } else {
#pragma unroll
            for (int i = 0; i < 8; i++)
                if (t0 + tr * 8 + i < LOUT) out[base + i] = acc[j][i];
        }
    }
    __syncthreads();
    for (int c = tid; c < COT; c += 256) {
        atomicAdd(&gsum[co0 + c], (double)sSum[c]);
        atomicAdd(&gsq[co0 + c],  (double)sSq[c]);
    }
}

// ---------------- tcgen05 tf32 3x-split conv (layers 2 & 3) ----------------
// grid: (3 t-tiles, COUT/128, B/4). One CTA: M=128 co x 4 batch sections of N=128 t.
// Accelerated (sm_103a) path uses tcgen05; generic pass compiles an fp32 fallback.
template<int CIN, int KW, int PAD>
__global__ __launch_bounds__(256, 1)
void conv_tc(const float* __restrict__ in, const float* __restrict__ wpacked,
             const float* __restrict__ bias,
             const float* __restrict__ bnS, const float* __restrict__ bnT,
             float* __restrict__ out,
             double* __restrict__ gsum, double* __restrict__ gsq) {
    constexpr int CK = 16, NB = 4, TT = 128;
    constexpr int RSEC   = TT + KW - 1;
    constexpr int NROWS  = NB * RSEC;
    constexpr int CHUNKS = CIN / CK;
    constexpr int XSPLIT = 4 * NROWS * 16;           // bytes per split (4 planes)
    constexpr int XOFF   = 64;
    constexpr int WOFF   = XOFF + 2 * XSPLIT;
    constexpr int WCHUNK_F = 2 * KW * 2048;          // floats per chunk (s,k,j,co,e)

    extern __shared__ char smem[];
    const int tid  = threadIdx.x;
    const int wid  = tid >> 5;
    const int lane = tid & 31;
    const int t0  = blockIdx.x * TT;
    const int co0 = blockIdx.y * 128;
    const int b0  = blockIdx.z * NB;
    const int COUT = gridDim.y * 128;
    const float* wpc = wpacked + (size_t)blockIdx.y * CHUNKS * WCHUNK_F;

#if HAS_TC
    const uint32_t sb = smem_u32(smem);
    if (tid == 0) MBARRIER_INIT(sb + 0, 1);
    if (wid == 0) TCGEN05_ALLOC(sb + 8, 512);
    __syncthreads();
    uint32_t tmem;
    asm volatile("ld.shared.b32 %0, [%1];" : "=r"(tmem) : "r"(sb + 8));

    int ph = 0;
    for (int c = 0; c < CHUNKS; c++) {
        if (c) { MBARRIER_WAIT_PARITY(sb + 0, ph); ph ^= 1; }
        // weights: flat copy (global layout already equals smem layout)
        {
            const float4* src = (const float4*)(wpc + (size_t)c * WCHUNK_F);
            float4* dst = (float4*)(smem + WOFF);
            for (int i = tid; i < WCHUNK_F / 4; i += 256) dst[i] = src[i];
        }
        // activations: BN+ReLU + tf32 hi/lo split, K-major 16B rows, 4 planes
        for (int it = tid; it < NB * 4 * RSEC; it += 256) {
            int r   = it % RSEC;
            int sj  = it / RSEC;
            int sec = sj >> 2;
            int j   = sj & 3;
            int t   = t0 - PAD + r;
            float4 hi4, lo4;
            float* hp = (float*)&hi4;
            float* lp = (float*)&lo4;
#pragma unroll
            for (int e = 0; e < 4; e++) {
                int ci = c * CK + j * 4 + e;
                float v = 0.f;
                if (t >= 0 && t < LOUT_) {
                    v = in[((size_t)(b0 + sec) * CIN + ci) * LSTR_ + t];
                    v = fmaxf(fmaf(bnS[ci], v, bnT[ci]), 0.f);
                }
                float h = rna_tf32(v);
                hp[e] = h;
                lp[e] = rna_tf32(v - h);
            }
            int off = XOFF + j * (NROWS * 16) + (sec * RSEC + r) * 16;
            *(float4*)(smem + off)          = hi4;
            *(float4*)(smem + off + XSPLIT) = lo4;
        }
        __syncthreads();
        if (tid == 0) {
            FENCE_PROXY_ASYNC();
#pragma unroll 1
            for (int sec = 0; sec < NB; sec++) {
                uint32_t dt = tmem + sec * TT;
#pragma unroll
                for (int p = 0; p < 3; p++) {
                    const int sA = (p == 2) ? 1 : 0;
                    const int sB = (p == 1) ? 1 : 0;
                    uint32_t abase = sb + WOFF + (uint32_t)(sA * KW) * 8192u;
                    uint32_t bbase = sb + XOFF + (uint32_t)sB * XSPLIT
                                   + (uint32_t)(sec * RSEC) * 16u;
#pragma unroll
                    for (int k = 0; k < KW; k++) {
#pragma unroll
                        for (int k2 = 0; k2 < 2; k2++) {
                            uint32_t aaddr = abase + (uint32_t)k * 8192u + (uint32_t)k2 * 4096u;
                            uint32_t baddr = bbase + (uint32_t)k * 16u
                                           + (uint32_t)k2 * (uint32_t)(2 * NROWS * 16);
                            uint64_t ad = mk_desc(aaddr, 128, 8);
                            uint64_t bd = mk_desc(baddr, NROWS, 8);
                            uint32_t en = (c == 0 && p == 0 && k == 0 && k2 == 0) ? 0u : 1u;
                            mma_tf32_ss(dt, ad, bd, IDESC_TF32, en);
                        }
                    }
                }
            }
            TCGEN05_COMMIT(sb + 0);
        }
        __syncthreads();
    }
    MBARRIER_WAIT_PARITY(sb + 0, ph);
    TCGEN05_FENCE_AFTER();

    // ---- epilogue: LDTM, +bias, BN stats, smem transpose, coalesced store ----
    const int co_loc   = (wid & 3) * 32 + lane;   // TMEM lane -> co
    const int colbase  = (wid >> 2) * 256;
    const float bv = bias[co0 + co_loc];
    float bsum = 0.f, bsq = 0.f;
    float* tsm = (float*)(smem + WOFF) + wid * (32 * 33);

    for (int batch = 0; batch < 8; batch++) {
        int col0  = colbase + batch * 32;
        int sec   = col0 >> 7;
        int toff0 = col0 & 127;
        uint32_t r[32];
        TCGEN05_LD_32X32B_X32(r, tmem + col0);
        TCGEN05_WAIT_LD();
        float v[32];
#pragma unroll
        for (int q = 0; q < 32; q++) {
            v[q] = __uint_as_float(r[q]) + bv;
            if (t0 + toff0 + q < LOUT_) { bsum += v[q]; bsq += v[q] * v[q]; }
        }
#pragma unroll
        for (int q = 0; q < 32; q++) tsm[lane * 33 + q] = v[q];
        __syncwarp();
        int t = t0 + toff0 + lane;
        if (t < LOUT_) {
            size_t base = ((size_t)(b0 + sec) * COUT + co0 + (wid & 3) * 32);
#pragma unroll
            for (int jj = 0; jj < 32; jj++)
                out[(base + jj) * LSTR_ + t] = tsm[jj * 33 + lane];
        }
        __syncwarp();
    }
    atomicAdd(&gsum[co0 + co_loc], (double)bsum);
    atomicAdd(&gsq [co0 + co_loc], (double)bsq);

    TCGEN05_FENCE_BEFORE();
    __syncthreads();
    if (tid == 0)
        asm volatile("mbarrier.inval.shared.b64 [%0];" :: "r"(sb + 0) : "memory");
    __syncthreads();
    if (wid == 0) {
        TCGEN05_RELINQUISH();
        TCGEN05_DEALLOC(tmem, 512);
    }
#else
    // ---------------- fp32 fallback (generic target; same math) ----------------
    constexpr int RSECP = RSEC + 5;
    float* As   = (float*)smem;                 // [CK][RSECP]
    float* Wsm  = As + CK * RSECP;              // [CK][KW][128]  (w = hi + lo)
    float* sSum = Wsm + CK * KW * 128;
    float* sSq  = sSum + 128;
    const int tc = tid & 15, tr = tid >> 4;

    if (tid < 128) { sSum[tid] = 0.f; sSq[tid] = 0.f; }
    __syncthreads();

    for (int sec = 0; sec < NB; sec++) {
        float acc[8][8];
#pragma unroll
        for (int j = 0; j < 8; j++)
#pragma unroll
            for (int i = 0; i < 8; i++) acc[j][i] = 0.f;

        for (int c = 0; c < CHUNKS; c++) {
            __syncthreads();
            for (int idx = tid; idx < CK * RSEC; idx += 256) {
                int ci = idx / RSEC, r = idx % RSEC;
                int t = t0 - PAD + r;
                float v = 0.f;
                int cig = c * CK + ci;
                if (t >= 0 && t < LOUT_) {
                    v = in[((size_t)(b0 + sec) * CIN + cig) * LSTR_ + t];
                    v = fmaxf(fmaf(bnS[cig], v, bnT[cig]), 0.f);
                }
                As[ci * RSECP + r] = v;
            }
            for (int idx = tid; idx < CK * KW * 128; idx += 256) {
                int co = idx & 127;
                int r  = idx >> 7;
                int k  = r % KW;
                int ci = r / KW;
                int j = ci >> 2, e = ci & 3;
                const float* base = wpc + (size_t)c * WCHUNK_F;
                float hi = base[((0 * KW + k) * 4 + j) * 512 + co * 4 + e];
                float lo = base[((1 * KW + k) * 4 + j) * 512 + co * 4 + e];
                Wsm[(ci * KW + k) * 128 + co] = hi + lo;
            }
            __syncthreads();
#pragma unroll 1
            for (int ci = 0; ci < CK; ci++) {
                float a[8 + KW - 1];
#pragma unroll
                for (int x = 0; x < 8 + KW - 1; x++)
                    a[x] = As[ci * RSECP + tr * 8 + x];
#pragma unroll
                for (int k = 0; k < KW; k++) {
                    float wv[8];
#pragma unroll
                    for (int j = 0; j < 8; j++)
                        wv[j] = Wsm[(ci * KW + k) * 128 + tc * 8 + j];
#pragma unroll
                    for (int j = 0; j < 8; j++)
#pragma unroll
                        for (int i = 0; i < 8; i++)
                            acc[j][i] = fmaf(wv[j], a[k + i], acc[j][i]);
                }
            }
        }
        // bias + stats + store
#pragma unroll
        for (int j = 0; j < 8; j++) {
            float bj = bias[co0 + tc * 8 + j];
            float s = 0.f, s2 = 0.f;
#pragma unroll
            for (int i = 0; i < 8; i++) {
                float v = acc[j][i] + bj;
                acc[j][i] = v;
                if (t0 + tr * 8 + i < LOUT_) { s += v; s2 += v * v; }
            }
            atomicAdd(&sSum[tc * 8 + j], s);
            atomicAdd(&sSq[tc * 8 + j], s2);
            size_t base = ((size_t)(b0 + sec) * COUT + co0 + tc * 8 + j) * LSTR_ + t0 + tr * 8;
#pragma unroll
            for (int i = 0; i < 8; i++)
                if (t0 + tr * 8 + i < LOUT_) out[base + i] = acc[j][i];
        }
    }
    __syncthreads();
    if (tid < 128) {
        atomicAdd(&gsum[co0 + tid], (double)sSum[tid]);
        atomicAdd(&gsq [co0 + tid], (double)sSq[tid]);
    }
#endif
}

// ---------------- pool + fc + offset head ----------------
__global__ void pool_fc_off(const float* __restrict__ y3,
                            const float* __restrict__ s3, const float* __restrict__ t3,
                            const float* __restrict__ fcw, const float* __restrict__ fcb,
                            const float* __restrict__ offw, const float* __restrict__ offb,
                            float* __restrict__ goff) {
    int b = blockIdx.x;
    int c = threadIdx.x;   // 128
    __shared__ float pooled[128];
    __shared__ float feat[128];

    const float* row = y3 + ((size_t)b * 128 + c) * LSTR_;
    float s = s3[c], t = t3[c], acc = 0.f;
    int i = 0;
    for (; i + 4 <= LOUT_; i += 4) {
        float4 v = *(const float4*)&row[i];
        acc += fmaxf(fmaf(s, v.x, t), 0.f) + fmaxf(fmaf(s, v.y, t), 0.f)
             + fmaxf(fmaf(s, v.z, t), 0.f) + fmaxf(fmaf(s, v.w, t), 0.f);
    }
    for (; i < LOUT_; i++) acc += fmaxf(fmaf(s, row[i], t), 0.f);
    pooled[c] = acc * (1.f / (float)LOUT_);
    __syncthreads();

    float f = fcb[c];
#pragma unroll 4
    for (int q = 0; q < 32; q++) {
        float4 w = *(const float4*)&fcw[c * 128 + 4 * q];
        float4 p = *(const float4*)&pooled[4 * q];
        f = fmaf(w.x, p.x, f); f = fmaf(w.y, p.y, f);
        f = fmaf(w.z, p.z, f); f = fmaf(w.w, p.w, f);
    }
    feat[c] = f;
    __syncthreads();

    float o = offb[c];
#pragma unroll 4
    for (int q = 0; q < 32; q++) {
        float4 w = *(const float4*)&offw[c * 128 + 4 * q];
        float4 p = *(const float4*)&feat[4 * q];
        o = fmaf(w.x, p.x, o); o = fmaf(w.y, p.y, o);
        o = fmaf(w.z, p.z, o); o = fmaf(w.w, p.w, o);
    }
    goff[(size_t)b * 128 + c] = tanhf(o);
}

// ---------------- distances + argmin + gather output ----------------
__global__ void dist_out(const float* __restrict__ x, const float* __restrict__ mask,
                         const float* __restrict__ protos, const float* __restrict__ goff,
                         float* __restrict__ out) {
    int b = blockIdx.x, tid = threadIdx.x;   // 256
    __shared__ float4 xs[TIN];
    __shared__ float  ms[TIN];
    __shared__ float  sdist[KPROT];
    __shared__ int    sbest;

    for (int t = tid; t < TIN; t += 256) {
        xs[t] = *(const float4*)&x[((size_t)b * TIN + t) * 4];
        ms[t] = mask[(size_t)b * TIN + t];
    }
    if (tid < KPROT) sdist[tid] = 0.f;
    __syncthreads();

    for (int k = 0; k < KPROT; k++) {
        float4 ov = *(const float4*)&goff[(size_t)b * 128 + k * 4];
        float local = 0.f;
        for (int t = tid; t < TIN; t += 256) {
            float4 p  = *(const float4*)&protos[((size_t)k * TIN + t) * 4];
            float4 xv = xs[t];
            float d0 = xv.x - p.x - ov.x;
            float d1 = xv.y - p.y - ov.y;
            float d2 = xv.z - p.z - ov.z;
            float d3 = xv.w - p.w - ov.w;
            local += ms[t] * (d0 * d0 + d1 * d1 + d2 * d2 + d3 * d3);
        }
#pragma unroll
        for (int o = 16; o; o >>= 1) local += __shfl_xor_sync(0xffffffffu, local, o);
        if ((tid & 31) == 0) atomicAdd(&sdist[k], local);
    }
    __syncthreads();
    if (tid < 32) {
        float v = sdist[tid];
        int  idx = tid;
#pragma unroll
        for (int o = 16; o; o >>= 1) {
            float v2 = __shfl_xor_sync(0xffffffffu, v, o);
            int  i2  = __shfl_xor_sync(0xffffffffu, idx, o);
            if (v2 < v || (v2 == v && i2 < idx)) { v = v2; idx = i2; }
        }
        if (tid == 0) sbest = idx;
    }
    __syncthreads();
    int best = sbest;
    float4 ob = *(const float4*)&goff[(size_t)b * 128 + best * 4];
    for (int t = tid; t < TIN; t += 256) {
        float4 p = *(const float4*)&protos[((size_t)best * TIN + t) * 4];
        *(float4*)&out[((size_t)b * TIN + t) * 4] =
            make_float4(p.x + ob.x, p.y + ob.y, p.z + ob.z, p.w + ob.w);
    }
}

// ---------------- launcher ----------------
extern "C" void kernel_launch(void* const* d_in, const int* in_sizes, int n_in,
                              void* d_out, int out_size) {
    (void)in_sizes; (void)n_in; (void)out_size;
    const float* x      = (const float*)d_in[0];
    const float* mask   = (const float*)d_in[2];
    const float* protos = (const float*)d_in[3];
    const float* w1  = (const float*)d_in[4];
    const float* b1  = (const float*)d_in[5];
    const float* g1  = (const float*)d_in[6];
    const float* be1 = (const float*)d_in[7];
    const float* w2  = (const float*)d_in[8];
    const float* b2  = (const float*)d_in[9];
    const float* g2  = (const float*)d_in[10];
    const float* be2 = (const float*)d_in[11];
    const float* w3  = (const float*)d_in[12];
    const float* b3  = (const float*)d_in[13];
    const float* g3  = (const float*)d_in[14];
    const float* be3 = (const float*)d_in[15];
    const float* fcw = (const float*)d_in[16];
    const float* fcb = (const float*)d_in[17];
    const float* offw = (const float*)d_in[18];
    const float* offb = (const float*)d_in[19];
    float* out = (float*)d_out;

    float *y1, *y2, *y3, *w1r, *w2p, *w3p, *bnS, *bnT, *goff;
    double *gsum, *gsq;
    cudaGetSymbolAddress((void**)&y1,  g_y1);
    cudaGetSymbolAddress((void**)&y2,  g_y2);
    cudaGetSymbolAddress((void**)&y3,  g_y3);
    cudaGetSymbolAddress((void**)&w1r, g_w1r);
    cudaGetSymbolAddress((void**)&w2p, g_w2p);
    cudaGetSymbolAddress((void**)&w3p, g_w3p);
    cudaGetSymbolAddress((void**)&gsum, g_sum);
    cudaGetSymbolAddress((void**)&gsq,  g_sq);
    cudaGetSymbolAddress((void**)&bnS, g_bnS);
    cudaGetSymbolAddress((void**)&bnT, g_bnT);
    cudaGetSymbolAddress((void**)&goff, g_off);

    // dynamic smem sizes for the tc convs (cover both tc and fallback needs)
    const int SMEM2 = 64 + 2 * (4 * (4 * 132) * 16) + 2 * 5 * 8192;  // 149568
    const int SMEM3 = 64 + 2 * (4 * (4 * 130) * 16) + 2 * 3 * 8192;  // 115776
    cudaFuncSetAttribute((const void*)conv_tc<128, 5, 2>,
                         cudaFuncAttributeMaxDynamicSharedMemorySize, SMEM2);
    cudaFuncSetAttribute((const void*)conv_tc<256, 3, 1>,
                         cudaFuncAttributeMaxDynamicSharedMemorySize, SMEM3);

    const double invN = 1.0 / ((double)B_ * (double)LOUT_);

    zero_stats<<<2, 256>>>(gsum, gsq);
    reorder_w<<<(128 * 4 * 8 + 255) / 256, 256>>>(w1, w1r, 128, 4, 8);
    pack_w<<<(327680 + 255) / 256, 256>>>(w2, w2p, 128, 5, 8, 327680);
    pack_w<<<(196608 + 255) / 256, 256>>>(w3, w3p, 256, 3, 16, 196608);

    dim3 gc1(3, 1, B_);
    conv_bn<true, 4, 128, 8, 4, 4><<<gc1, 256>>>(
        x, w1r, b1, nullptr, nullptr, y1, gsum, gsq, TIN, 0, LOUT_, LSTR_);
    finalize_bn<<<1, 256>>>(gsum, gsq, g1, be1, bnS, bnT, 128, invN);

    dim3 gc2(3, 2, B_ / 4);
    conv_tc<128, 5, 2><<<gc2, 256, SMEM2>>>(
        y1, w2p, b2, bnS, bnT, y2, gsum + 128, gsq + 128);
    finalize_bn<<<1, 256>>>(gsum + 128, gsq + 128, g2, be2, bnS + 128, bnT + 128, 256, invN);

    dim3 gc3(3, 1, B_ / 4);
    conv_tc<256, 3, 1><<<gc3, 256, SMEM3>>>(
        y2, w3p, b3, bnS + 128, bnT + 128, y3, gsum + 384, gsq + 384);
    finalize_bn<<<1, 256>>>(gsum + 384, gsq + 384, g3, be3, bnS + 384, bnT + 384, 128, invN);

    pool_fc_off<<<B_, 128>>>(y3, bnS + 384, bnT + 384, fcw, fcb, offw, offb, goff);
    dist_out<<<B_, 256>>>(x, mask, protos, goff, out);
}